// round 1
// baseline (speedup 1.0000x reference)
#include <cuda_runtime.h>
#include <math.h>

#define DMODEL 768
#define NHEAD  12
#define DH     64
#define TAU    300.0f
#define NEGV   (-1e9f)
#define SCALE  0.125f   /* 1/sqrt(64) */

#define MAXM (64 * 512)

// Scratch (allocation-free): Q, K, V, attn-out. Projected output reuses g_Q.
__device__ float g_Q[MAXM * DMODEL];
__device__ float g_K[MAXM * DMODEL];
__device__ float g_V[MAXM * DMODEL];
__device__ float g_O[MAXM * DMODEL];

// ---------------------------------------------------------------------------
// C[M,N] = A[M,K] @ W[N,K]^T + bias[N]; optionally * maskp[m]
// 64x64 tile, BK=16, 256 threads, 4x4 microtile, float4 shared reads.
// ---------------------------------------------------------------------------
__global__ __launch_bounds__(256) void gemm_bias_mask(
    const float* __restrict__ A, const float* __restrict__ W,
    const float* __restrict__ bias, const float* __restrict__ maskp,
    float* __restrict__ C, int M, int N, int K)
{
    __shared__ float As[16][68];   // [k][m], pad keeps 16B alignment (68*4=272)
    __shared__ float Bs[16][68];   // [k][n]
    const int n0 = blockIdx.x * 64;
    const int m0 = blockIdx.y * 64;
    const int t  = threadIdx.x;
    const int tx = t & 15, ty = t >> 4;

    float acc[4][4];
#pragma unroll
    for (int i = 0; i < 4; i++)
#pragma unroll
        for (int j = 0; j < 4; j++) acc[i][j] = 0.0f;

    for (int k0 = 0; k0 < K; k0 += 16) {
#pragma unroll
        for (int i = 0; i < 4; i++) {
            int idx = t + i * 256;          // 0..1023
            int r = idx >> 4, c = idx & 15;
            As[c][r] = A[(size_t)(m0 + r) * K + (k0 + c)];
            Bs[c][r] = W[(size_t)(n0 + r) * K + (k0 + c)];
        }
        __syncthreads();
#pragma unroll
        for (int kk = 0; kk < 16; kk++) {
            float4 a4 = *(const float4*)&As[kk][ty * 4];
            float4 b4 = *(const float4*)&Bs[kk][tx * 4];
            float av[4] = {a4.x, a4.y, a4.z, a4.w};
            float bv[4] = {b4.x, b4.y, b4.z, b4.w};
#pragma unroll
            for (int i = 0; i < 4; i++)
#pragma unroll
                for (int j = 0; j < 4; j++)
                    acc[i][j] = fmaf(av[i], bv[j], acc[i][j]);
        }
        __syncthreads();
    }

    const int nn = n0 + tx * 4;
    float b0 = bias[nn + 0], b1 = bias[nn + 1], b2 = bias[nn + 2], b3 = bias[nn + 3];
#pragma unroll
    for (int i = 0; i < 4; i++) {
        int m = m0 + ty * 4 + i;
        float mk = maskp ? maskp[m] : 1.0f;
        float4 v;
        v.x = (acc[i][0] + b0) * mk;
        v.y = (acc[i][1] + b1) * mk;
        v.z = (acc[i][2] + b2) * mk;
        v.w = (acc[i][3] + b3) * mk;
        *(float4*)&C[(size_t)m * N + nn] = v;
    }
}

// ---------------------------------------------------------------------------
// Flash-style attention per (q-tile=64, head, batch). 256 threads = 8 warps;
// each warp owns 8 query rows; each lane owns 2 key-cols (scores) / 2 out-dims.
// Bias = log(exp(-|t_q - t_k|/tau) + 1e-12); padded keys -> -1e9.
// ---------------------------------------------------------------------------
__global__ __launch_bounds__(256) void attn_kernel(
    const float* __restrict__ Q, const float* __restrict__ K,
    const float* __restrict__ V, const float* __restrict__ ts,
    const float* __restrict__ maskp, float* __restrict__ O, int L)
{
    extern __shared__ float sm[];
    float* Qs  = sm;               // 64x64   (pre-scaled)
    float* Kst = Qs  + 4096;       // 64x66   [d][k] transposed, padded
    float* Vs  = Kst + 4224;       // 64x64   [k][d]
    float* Ps  = Vs  + 4096;       // 8x8x64  [warp][r][k]
    float* tqs = Ps  + 4096;       // 64
    float* tks = tqs + 64;         // 64
    float* mks = tks + 64;         // 64

    const int qt = blockIdx.x, h = blockIdx.y, n = blockIdx.z;
    const int t = threadIdx.x, w = t >> 5, lane = t & 31;
    const int q0 = qt * 64;
    const size_t base = (size_t)n * L * DMODEL + (size_t)h * DH;

    for (int i = t; i < 4096; i += 256) {
        int r = i >> 6, d = i & 63;
        Qs[i] = Q[base + (size_t)(q0 + r) * DMODEL + d] * SCALE;
    }
    if (t < 64) tqs[t] = ts[n * L + q0 + t];

    float m_r[8], l_r[8], a0[8], a1[8];
#pragma unroll
    for (int r = 0; r < 8; r++) { m_r[r] = -1e30f; l_r[r] = 0.f; a0[r] = 0.f; a1[r] = 0.f; }

    const int nchunk = L / 64;
    for (int c = 0; c < nchunk; c++) {
        const int k0 = c * 64;
        __syncthreads();   // also covers Qs/tqs init at c==0, Kst/Vs reuse after
        for (int i = t; i < 4096; i += 256) {
            int kk = i >> 6, d = i & 63;
            size_t g = base + (size_t)(k0 + kk) * DMODEL + d;
            Kst[d * 66 + kk] = K[g];
            Vs[i] = V[g];
        }
        if (t < 64) {
            tks[t] = ts[n * L + k0 + t];
            mks[t] = maskp[n * L + k0 + t];
        }
        __syncthreads();

        // ---- scores: 8 rows, 2 key cols per lane ----
        float s0[8], s1[8];
#pragma unroll
        for (int r = 0; r < 8; r++) { s0[r] = 0.f; s1[r] = 0.f; }
        const float* qbase = Qs + (w * 8) * 64;
#pragma unroll 4
        for (int d = 0; d < 64; d++) {
            float k0v = Kst[d * 66 + lane];
            float k1v = Kst[d * 66 + lane + 32];
#pragma unroll
            for (int r = 0; r < 8; r++) {
                float qv = qbase[r * 64 + d];
                s0[r] = fmaf(qv, k0v, s0[r]);
                s1[r] = fmaf(qv, k1v, s1[r]);
            }
        }

        const float mk0 = mks[lane], mk1 = mks[lane + 32];
        const float tk0 = tks[lane], tk1 = tks[lane + 32];
        float corr[8];
#pragma unroll
        for (int r = 0; r < 8; r++) {
            float tq = tqs[w * 8 + r];
            float b0 = logf(expf(-fabsf(tq - tk0) * (1.0f / TAU)) + 1e-12f);
            float b1 = logf(expf(-fabsf(tq - tk1) * (1.0f / TAU)) + 1e-12f);
            float v0 = (mk0 > 0.f) ? s0[r] + b0 : NEGV;
            float v1 = (mk1 > 0.f) ? s1[r] + b1 : NEGV;
            float mx = fmaxf(v0, v1);
#pragma unroll
            for (int o = 16; o > 0; o >>= 1) mx = fmaxf(mx, __shfl_xor_sync(0xffffffffu, mx, o));
            float nm = fmaxf(m_r[r], mx);
            float cr = expf(m_r[r] - nm);
            float p0 = expf(v0 - nm);
            float p1 = expf(v1 - nm);
            float ps = p0 + p1;
#pragma unroll
            for (int o = 16; o > 0; o >>= 1) ps += __shfl_xor_sync(0xffffffffu, ps, o);
            l_r[r] = l_r[r] * cr + ps;
            m_r[r] = nm;
            corr[r] = cr;
            Ps[(w * 8 + r) * 64 + lane]      = p0;
            Ps[(w * 8 + r) * 64 + lane + 32] = p1;
        }
        __syncwarp();

        // ---- A @ V accumulation: lane owns dims (lane, lane+32) ----
#pragma unroll
        for (int r = 0; r < 8; r++) { a0[r] *= corr[r]; a1[r] *= corr[r]; }
        const float* pbase = Ps + (w * 8) * 64;
#pragma unroll 2
        for (int kk = 0; kk < 64; kk++) {
            float v0 = Vs[kk * 64 + lane];
            float v1 = Vs[kk * 64 + lane + 32];
#pragma unroll
            for (int r = 0; r < 8; r++) {
                float p = pbase[r * 64 + kk];
                a0[r] = fmaf(p, v0, a0[r]);
                a1[r] = fmaf(p, v1, a1[r]);
            }
        }
    }

#pragma unroll
    for (int r = 0; r < 8; r++) {
        int qr = w * 8 + r;
        float inv = 1.0f / l_r[r];
        size_t g = base + (size_t)(q0 + qr) * DMODEL;
        O[g + lane]      = a0[r] * inv;
        O[g + lane + 32] = a1[r] * inv;
    }
}

// ---------------------------------------------------------------------------
// Readout pooling: one block per (head, batch). X = masked projected output.
// ---------------------------------------------------------------------------
__global__ __launch_bounds__(256) void pool_kernel(
    const float* __restrict__ X, const float* __restrict__ readout,
    const float* __restrict__ maskp, float* __restrict__ out, int L)
{
    __shared__ float s[512];
    __shared__ float qsh[64];
    __shared__ float red[8];
    __shared__ float part[8][64];
    const int h = blockIdx.x, n = blockIdx.y;
    const int t = threadIdx.x, w = t >> 5, lane = t & 31;
    if (t < 64) qsh[t] = readout[h * DH + t] * SCALE;
    __syncthreads();
    const size_t base = (size_t)n * L * DMODEL + (size_t)h * DH;

    // scores: one warp per key row (strided)
    for (int k = w; k < L; k += 8) {
        float d = X[base + (size_t)k * DMODEL + lane] * qsh[lane]
                + X[base + (size_t)k * DMODEL + lane + 32] * qsh[lane + 32];
#pragma unroll
        for (int o = 16; o > 0; o >>= 1) d += __shfl_xor_sync(0xffffffffu, d, o);
        if (lane == 0) s[k] = (maskp[n * L + k] > 0.f) ? d : NEGV;
    }
    __syncthreads();

    // block softmax
    float lm = -1e30f;
    for (int k = t; k < L; k += 256) lm = fmaxf(lm, s[k]);
#pragma unroll
    for (int o = 16; o > 0; o >>= 1) lm = fmaxf(lm, __shfl_xor_sync(0xffffffffu, lm, o));
    if (lane == 0) red[w] = lm;
    __syncthreads();
    float gm = red[0];
#pragma unroll
    for (int i = 1; i < 8; i++) gm = fmaxf(gm, red[i]);
    __syncthreads();   // all red reads done before reuse
    float ls = 0.f;
    for (int k = t; k < L; k += 256) { float p = expf(s[k] - gm); s[k] = p; ls += p; }
#pragma unroll
    for (int o = 16; o > 0; o >>= 1) ls += __shfl_xor_sync(0xffffffffu, ls, o);
    if (lane == 0) red[w] = ls;
    __syncthreads();
    float gs = 0.f;
#pragma unroll
    for (int i = 0; i < 8; i++) gs += red[i];
    float inv = 1.0f / gs;

    // weighted sum: warp w handles key range [w*L/8, (w+1)*L/8)
    const int kb = w * (L / 8), ke = kb + (L / 8);
    float a0 = 0.f, a1 = 0.f;
    for (int k = kb; k < ke; k++) {
        float p = s[k];
        a0 = fmaf(p, X[base + (size_t)k * DMODEL + lane], a0);
        a1 = fmaf(p, X[base + (size_t)k * DMODEL + lane + 32], a1);
    }
    part[w][lane]      = a0;
    part[w][lane + 32] = a1;
    __syncthreads();
    if (t < 64) {
        float sum = 0.f;
#pragma unroll
        for (int i = 0; i < 8; i++) sum += part[i][t];
        out[(size_t)n * DMODEL + h * DH + t] = sum * inv;
    }
}

// ---------------------------------------------------------------------------
extern "C" void kernel_launch(void* const* d_in, const int* in_sizes, int n_in,
                              void* d_out, int out_size)
{
    const float* tokens  = (const float*)d_in[0];
    const float* ts      = (const float*)d_in[1];
    const float* maskp   = (const float*)d_in[2];
    const float* Wq      = (const float*)d_in[3];
    const float* bq      = (const float*)d_in[4];
    const float* Wk      = (const float*)d_in[5];
    const float* bk      = (const float*)d_in[6];
    const float* Wv      = (const float*)d_in[7];
    const float* bv      = (const float*)d_in[8];
    const float* Wo      = (const float*)d_in[9];
    const float* bo      = (const float*)d_in[10];
    const float* readout = (const float*)d_in[11];
    float* out = (float*)d_out;
    (void)n_in;

    const int M  = in_sizes[0] / DMODEL;   // N*L = 32768
    const int Nb = out_size / DMODEL;      // 64
    const int L  = M / Nb;                 // 512

    float *gQ, *gK, *gV, *gO;
    cudaGetSymbolAddress((void**)&gQ, g_Q);
    cudaGetSymbolAddress((void**)&gK, g_K);
    cudaGetSymbolAddress((void**)&gV, g_V);
    cudaGetSymbolAddress((void**)&gO, g_O);

    dim3 gg(DMODEL / 64, M / 64);
    gemm_bias_mask<<<gg, 256>>>(tokens, Wq, bq, nullptr, gQ, M, DMODEL, DMODEL);
    gemm_bias_mask<<<gg, 256>>>(tokens, Wk, bk, nullptr, gK, M, DMODEL, DMODEL);
    gemm_bias_mask<<<gg, 256>>>(tokens, Wv, bv, nullptr, gV, M, DMODEL, DMODEL);

    const int smem = (4096 + 4224 + 4096 + 4096 + 192) * 4;   // 66816 B
    cudaFuncSetAttribute(attn_kernel, cudaFuncAttributeMaxDynamicSharedMemorySize, smem);
    dim3 ag(L / 64, NHEAD, Nb);
    attn_kernel<<<ag, 256, smem>>>(gQ, gK, gV, ts, maskp, gO, L);

    // projected + masked output reuses g_Q
    gemm_bias_mask<<<gg, 256>>>(gO, Wo, bo, maskp, gQ, M, DMODEL, DMODEL);

    dim3 pg(NHEAD, Nb);
    pool_kernel<<<pg, 256>>>(gQ, readout, maskp, out, L);
}

// round 3
// speedup vs baseline: 1.6448x; 1.6448x over previous
#include <cuda_runtime.h>
#include <cuda_bf16.h>
#include <math.h>
#include <stdint.h>

#define DMODEL 768
#define NHEAD  12
#define DH     64
#define TAU    300.0f
#define NEGV   (-1e9f)
#define SCALE  0.125f   /* 1/sqrt(64) */

#define MAXM (64 * 512)

// Scratch (allocation-free): Q, K, V, attn-out. Projected output reuses g_Q.
__device__ float g_Q[MAXM * DMODEL];
__device__ float g_K[MAXM * DMODEL];
__device__ float g_V[MAXM * DMODEL];
__device__ float g_O[MAXM * DMODEL];

// ===========================================================================
// mma.sync / ldmatrix helpers (arch-portable tensor-core path; HMMA on sm_103a)
// ===========================================================================
__device__ __forceinline__ uint32_t smem_u32(const void* p) {
    uint32_t a;
    asm("{ .reg .u64 t; cvta.to.shared.u64 t, %1; cvt.u32.u64 %0, t; }"
        : "=r"(a) : "l"(p));
    return a;
}

__device__ __forceinline__ void ldsm4(uint32_t* r, uint32_t addr) {
    asm volatile("ldmatrix.sync.aligned.m8n8.x4.shared.b16 {%0,%1,%2,%3}, [%4];"
                 : "=r"(r[0]), "=r"(r[1]), "=r"(r[2]), "=r"(r[3]) : "r"(addr));
}

__device__ __forceinline__ void mma16816(float* c, const uint32_t* a,
                                         const uint32_t* b) {
    asm volatile(
        "mma.sync.aligned.m16n8k16.row.col.f32.bf16.bf16.f32 "
        "{%0,%1,%2,%3}, {%4,%5,%6,%7}, {%8,%9}, {%0,%1,%2,%3};"
        : "+f"(c[0]), "+f"(c[1]), "+f"(c[2]), "+f"(c[3])
        : "r"(a[0]), "r"(a[1]), "r"(a[2]), "r"(a[3]), "r"(b[0]), "r"(b[1]));
}

__device__ __forceinline__ void split4(float4 v, uint2& h, uint2& l) {
    __nv_bfloat16 h0 = __float2bfloat16_rn(v.x);
    __nv_bfloat16 h1 = __float2bfloat16_rn(v.y);
    __nv_bfloat16 h2 = __float2bfloat16_rn(v.z);
    __nv_bfloat16 h3 = __float2bfloat16_rn(v.w);
    __nv_bfloat16 l0 = __float2bfloat16_rn(v.x - __bfloat162float(h0));
    __nv_bfloat16 l1 = __float2bfloat16_rn(v.y - __bfloat162float(h1));
    __nv_bfloat16 l2 = __float2bfloat16_rn(v.z - __bfloat162float(h2));
    __nv_bfloat16 l3 = __float2bfloat16_rn(v.w - __bfloat162float(h3));
    h.x = (uint32_t)__bfloat16_as_ushort(h0) | ((uint32_t)__bfloat16_as_ushort(h1) << 16);
    h.y = (uint32_t)__bfloat16_as_ushort(h2) | ((uint32_t)__bfloat16_as_ushort(h3) << 16);
    l.x = (uint32_t)__bfloat16_as_ushort(l0) | ((uint32_t)__bfloat16_as_ushort(l1) << 16);
    l.y = (uint32_t)__bfloat16_as_ushort(l2) | ((uint32_t)__bfloat16_as_ushort(l3) << 16);
}

// ===========================================================================
// HMMA GEMM: C[M,N] = A[M,K] @ W[N,K]^T + bias[N], optionally * maskp[m]
// 3-term bf16 split, fp32 accumulate. CTA 128x128, BK=32, 256 threads.
// Smem pitch 80B/row -> conflict-free ldmatrix (banks 20r mod 32 disjoint).
// ===========================================================================
#define GBM 128
#define GBN 128
#define GBK 32
#define GPITCH 40   /* bf16 elems per row (80 bytes) */

__global__ __launch_bounds__(256, 1) void gemm_tc(
    const float* __restrict__ A, const float* __restrict__ W,
    const float* __restrict__ bias, const float* __restrict__ maskp,
    float* __restrict__ C, int M, int N, int K)
{
    __shared__ __nv_bfloat16 Ah[GBM * GPITCH], Al[GBM * GPITCH];
    __shared__ __nv_bfloat16 Bh[GBN * GPITCH], Bl[GBN * GPITCH];
    __shared__ float bias_s[GBN];

    const int t = threadIdx.x;
    const int wid = t >> 5, lane = t & 31;
    const int n0 = blockIdx.x * GBN;
    const int m0 = blockIdx.y * GBM;

    if (t < GBN) bias_s[t] = bias[n0 + t];

    // ---- loader mapping: 32 rows x 8 col-groups, 4 f32 per thread ----
    const int lr = t >> 3;          // 0..31
    const int lc = t & 7;           // 0..7
    const float* Abase = A + (size_t)(m0 + lr) * K + lc * 4;
    const float* Wbase = W + (size_t)(n0 + lr) * K + lc * 4;

    float4 pa[4], pb[4];
    const int NITER = K / GBK;

    // prologue: prefetch iter 0
#pragma unroll
    for (int i = 0; i < 4; i++) {
        pa[i] = *(const float4*)(Abase + (size_t)(32 * i) * K);
        pb[i] = *(const float4*)(Wbase + (size_t)(32 * i) * K);
    }

    // ---- compute mapping ----
    const int wm = wid >> 2;        // 0..1  (64-row slab)
    const int wn = wid & 3;         // 0..3  (32-col slab)
    const uint32_t ah_s = smem_u32(Ah), al_s = smem_u32(Al);
    const uint32_t bh_s = smem_u32(Bh), bl_s = smem_u32(Bl);
    // ldmatrix lane address components
    const int a_row = lane & 15;                    // rows 0..15 within m16 tile
    const int a_chk = (lane >> 4) & 1;              // k-halves (16B)
    const int b_n   = (lane & 7) + ((lane >> 4) & 1) * 8;  // n row within n16 pair
    const int b_chk = (lane >> 3) & 1;

    float acc[4][4][4];
#pragma unroll
    for (int mi = 0; mi < 4; mi++)
#pragma unroll
        for (int ni = 0; ni < 4; ni++)
#pragma unroll
            for (int j = 0; j < 4; j++) acc[mi][ni][j] = 0.0f;

    for (int it = 0; it < NITER; it++) {
        // store prefetched slab (with hi/lo split)
#pragma unroll
        for (int i = 0; i < 4; i++) {
            int idx = (lr + 32 * i) * GPITCH + lc * 4;
            uint2 h, l;
            split4(pa[i], h, l);
            *(uint2*)&Ah[idx] = h;
            *(uint2*)&Al[idx] = l;
            split4(pb[i], h, l);
            *(uint2*)&Bh[idx] = h;
            *(uint2*)&Bl[idx] = l;
        }
        __syncthreads();

        // prefetch next slab (overlaps with MMA below)
        if (it + 1 < NITER) {
            const float* An = Abase + (size_t)(it + 1) * GBK;
            const float* Wn = Wbase + (size_t)(it + 1) * GBK;
#pragma unroll
            for (int i = 0; i < 4; i++) {
                pa[i] = *(const float4*)(An + (size_t)(32 * i) * K);
                pb[i] = *(const float4*)(Wn + (size_t)(32 * i) * K);
            }
        }

#pragma unroll
        for (int s = 0; s < 2; s++) {
            const uint32_t koff = s * 32 + 16 * 0;  // base k byte offset for this step
            // B fragments: 4 n8 frags per term
            uint32_t bhf[8], blf[8];
#pragma unroll
            for (int nt = 0; nt < 2; nt++) {
                uint32_t boff = (uint32_t)(wn * 32 + nt * 16 + b_n) * 80
                              + s * 32 + b_chk * 16;
                ldsm4(bhf + nt * 4, bh_s + boff);
                ldsm4(blf + nt * 4, bl_s + boff);
            }
#pragma unroll
            for (int mi = 0; mi < 4; mi++) {
                uint32_t aoff = (uint32_t)(wm * 64 + mi * 16 + a_row) * 80
                              + s * 32 + a_chk * 16;
                uint32_t ahf[4], alf[4];
                ldsm4(ahf, ah_s + aoff);
                ldsm4(alf, al_s + aoff);
#pragma unroll
                for (int ni = 0; ni < 4; ni++) {
                    mma16816(acc[mi][ni], ahf, bhf + ni * 2);
                    mma16816(acc[mi][ni], ahf, blf + ni * 2);
                    mma16816(acc[mi][ni], alf, bhf + ni * 2);
                }
            }
            (void)koff;
        }
        __syncthreads();
    }

    // ---- epilogue: bias + optional mask, direct to gmem ----
    const int r0 = lane >> 2;            // 0..7
    const int c0 = (lane & 3) * 2;       // 0,2,4,6
#pragma unroll
    for (int mi = 0; mi < 4; mi++) {
        int mA = m0 + wm * 64 + mi * 16 + r0;
        int mB = mA + 8;
        float mkA = maskp ? maskp[mA] : 1.0f;
        float mkB = maskp ? maskp[mB] : 1.0f;
#pragma unroll
        for (int ni = 0; ni < 4; ni++) {
            int n = wn * 32 + ni * 8 + c0;
            float b0 = bias_s[n], b1 = bias_s[n + 1];
            float2 vA, vB;
            vA.x = (acc[mi][ni][0] + b0) * mkA;
            vA.y = (acc[mi][ni][1] + b1) * mkA;
            vB.x = (acc[mi][ni][2] + b0) * mkB;
            vB.y = (acc[mi][ni][3] + b1) * mkB;
            *(float2*)&C[(size_t)mA * N + n0 + n] = vA;
            *(float2*)&C[(size_t)mB * N + n0 + n] = vB;
        }
    }
}

// ---------------------------------------------------------------------------
// Flash-style attention per (q-tile=64, head, batch). 256 threads = 8 warps;
// each warp owns 8 query rows; each lane owns 2 key-cols (scores) / 2 out-dims.
// Bias = log(exp(-|t_q - t_k|/tau) + 1e-12); padded keys -> -1e9.
// ---------------------------------------------------------------------------
__global__ __launch_bounds__(256) void attn_kernel(
    const float* __restrict__ Q, const float* __restrict__ K,
    const float* __restrict__ V, const float* __restrict__ ts,
    const float* __restrict__ maskp, float* __restrict__ O, int L)
{
    extern __shared__ float sm[];
    float* Qs  = sm;               // 64x64   (pre-scaled)
    float* Kst = Qs  + 4096;       // 64x66   [d][k] transposed, padded
    float* Vs  = Kst + 4224;       // 64x64   [k][d]
    float* Ps  = Vs  + 4096;       // 8x8x64  [warp][r][k]
    float* tqs = Ps  + 4096;       // 64
    float* tks = tqs + 64;         // 64
    float* mks = tks + 64;         // 64

    const int qt = blockIdx.x, h = blockIdx.y, n = blockIdx.z;
    const int t = threadIdx.x, w = t >> 5, lane = t & 31;
    const int q0 = qt * 64;
    const size_t base = (size_t)n * L * DMODEL + (size_t)h * DH;

    for (int i = t; i < 4096; i += 256) {
        int r = i >> 6, d = i & 63;
        Qs[i] = Q[base + (size_t)(q0 + r) * DMODEL + d] * SCALE;
    }
    if (t < 64) tqs[t] = ts[n * L + q0 + t];

    float m_r[8], l_r[8], a0[8], a1[8];
#pragma unroll
    for (int r = 0; r < 8; r++) { m_r[r] = -1e30f; l_r[r] = 0.f; a0[r] = 0.f; a1[r] = 0.f; }

    const int nchunk = L / 64;
    for (int c = 0; c < nchunk; c++) {
        const int k0 = c * 64;
        __syncthreads();   // also covers Qs/tqs init at c==0, Kst/Vs reuse after
        for (int i = t; i < 4096; i += 256) {
            int kk = i >> 6, d = i & 63;
            size_t g = base + (size_t)(k0 + kk) * DMODEL + d;
            Kst[d * 66 + kk] = K[g];
            Vs[i] = V[g];
        }
        if (t < 64) {
            tks[t] = ts[n * L + k0 + t];
            mks[t] = maskp[n * L + k0 + t];
        }
        __syncthreads();

        // ---- scores: 8 rows, 2 key cols per lane ----
        float s0[8], s1[8];
#pragma unroll
        for (int r = 0; r < 8; r++) { s0[r] = 0.f; s1[r] = 0.f; }
        const float* qbase = Qs + (w * 8) * 64;
#pragma unroll 4
        for (int d = 0; d < 64; d++) {
            float k0v = Kst[d * 66 + lane];
            float k1v = Kst[d * 66 + lane + 32];
#pragma unroll
            for (int r = 0; r < 8; r++) {
                float qv = qbase[r * 64 + d];
                s0[r] = fmaf(qv, k0v, s0[r]);
                s1[r] = fmaf(qv, k1v, s1[r]);
            }
        }

        const float mk0 = mks[lane], mk1 = mks[lane + 32];
        const float tk0 = tks[lane], tk1 = tks[lane + 32];
        float corr[8];
#pragma unroll
        for (int r = 0; r < 8; r++) {
            float tq = tqs[w * 8 + r];
            float b0 = logf(expf(-fabsf(tq - tk0) * (1.0f / TAU)) + 1e-12f);
            float b1 = logf(expf(-fabsf(tq - tk1) * (1.0f / TAU)) + 1e-12f);
            float v0 = (mk0 > 0.f) ? s0[r] + b0 : NEGV;
            float v1 = (mk1 > 0.f) ? s1[r] + b1 : NEGV;
            float mx = fmaxf(v0, v1);
#pragma unroll
            for (int o = 16; o > 0; o >>= 1) mx = fmaxf(mx, __shfl_xor_sync(0xffffffffu, mx, o));
            float nm = fmaxf(m_r[r], mx);
            float cr = expf(m_r[r] - nm);
            float p0 = expf(v0 - nm);
            float p1 = expf(v1 - nm);
            float ps = p0 + p1;
#pragma unroll
            for (int o = 16; o > 0; o >>= 1) ps += __shfl_xor_sync(0xffffffffu, ps, o);
            l_r[r] = l_r[r] * cr + ps;
            m_r[r] = nm;
            corr[r] = cr;
            Ps[(w * 8 + r) * 64 + lane]      = p0;
            Ps[(w * 8 + r) * 64 + lane + 32] = p1;
        }
        __syncwarp();

        // ---- A @ V accumulation: lane owns dims (lane, lane+32) ----
#pragma unroll
        for (int r = 0; r < 8; r++) { a0[r] *= corr[r]; a1[r] *= corr[r]; }
        const float* pbase = Ps + (w * 8) * 64;
#pragma unroll 2
        for (int kk = 0; kk < 64; kk++) {
            float v0 = Vs[kk * 64 + lane];
            float v1 = Vs[kk * 64 + lane + 32];
#pragma unroll
            for (int r = 0; r < 8; r++) {
                float p = pbase[r * 64 + kk];
                a0[r] = fmaf(p, v0, a0[r]);
                a1[r] = fmaf(p, v1, a1[r]);
            }
        }
    }

#pragma unroll
    for (int r = 0; r < 8; r++) {
        int qr = w * 8 + r;
        float inv = 1.0f / l_r[r];
        size_t g = base + (size_t)(q0 + qr) * DMODEL;
        O[g + lane]      = a0[r] * inv;
        O[g + lane + 32] = a1[r] * inv;
    }
}

// ---------------------------------------------------------------------------
// Readout pooling: one block per (head, batch). X = masked projected output.
// ---------------------------------------------------------------------------
__global__ __launch_bounds__(256) void pool_kernel(
    const float* __restrict__ X, const float* __restrict__ readout,
    const float* __restrict__ maskp, float* __restrict__ out, int L)
{
    __shared__ float s[512];
    __shared__ float qsh[64];
    __shared__ float red[8];
    __shared__ float part[8][64];
    const int h = blockIdx.x, n = blockIdx.y;
    const int t = threadIdx.x, w = t >> 5, lane = t & 31;
    if (t < 64) qsh[t] = readout[h * DH + t] * SCALE;
    __syncthreads();
    const size_t base = (size_t)n * L * DMODEL + (size_t)h * DH;

    // scores: one warp per key row (strided)
    for (int k = w; k < L; k += 8) {
        float d = X[base + (size_t)k * DMODEL + lane] * qsh[lane]
                + X[base + (size_t)k * DMODEL + lane + 32] * qsh[lane + 32];
#pragma unroll
        for (int o = 16; o > 0; o >>= 1) d += __shfl_xor_sync(0xffffffffu, d, o);
        if (lane == 0) s[k] = (maskp[n * L + k] > 0.f) ? d : NEGV;
    }
    __syncthreads();

    // block softmax
    float lm = -1e30f;
    for (int k = t; k < L; k += 256) lm = fmaxf(lm, s[k]);
#pragma unroll
    for (int o = 16; o > 0; o >>= 1) lm = fmaxf(lm, __shfl_xor_sync(0xffffffffu, lm, o));
    if (lane == 0) red[w] = lm;
    __syncthreads();
    float gm = red[0];
#pragma unroll
    for (int i = 1; i < 8; i++) gm = fmaxf(gm, red[i]);
    __syncthreads();   // all red reads done before reuse
    float ls = 0.f;
    for (int k = t; k < L; k += 256) { float p = expf(s[k] - gm); s[k] = p; ls += p; }
#pragma unroll
    for (int o = 16; o > 0; o >>= 1) ls += __shfl_xor_sync(0xffffffffu, ls, o);
    if (lane == 0) red[w] = ls;
    __syncthreads();
    float gs = 0.f;
#pragma unroll
    for (int i = 0; i < 8; i++) gs += red[i];
    float inv = 1.0f / gs;

    // weighted sum: warp w handles key range [w*L/8, (w+1)*L/8)
    const int kb = w * (L / 8), ke = kb + (L / 8);
    float a0 = 0.f, a1 = 0.f;
    for (int k = kb; k < ke; k++) {
        float p = s[k];
        a0 = fmaf(p, X[base + (size_t)k * DMODEL + lane], a0);
        a1 = fmaf(p, X[base + (size_t)k * DMODEL + lane + 32], a1);
    }
    part[w][lane]      = a0;
    part[w][lane + 32] = a1;
    __syncthreads();
    if (t < 64) {
        float sum = 0.f;
#pragma unroll
        for (int i = 0; i < 8; i++) sum += part[i][t];
        out[(size_t)n * DMODEL + h * DH + t] = sum * inv;
    }
}

// ---------------------------------------------------------------------------
extern "C" void kernel_launch(void* const* d_in, const int* in_sizes, int n_in,
                              void* d_out, int out_size)
{
    const float* tokens  = (const float*)d_in[0];
    const float* ts      = (const float*)d_in[1];
    const float* maskp   = (const float*)d_in[2];
    const float* Wq      = (const float*)d_in[3];
    const float* bq      = (const float*)d_in[4];
    const float* Wk      = (const float*)d_in[5];
    const float* bk      = (const float*)d_in[6];
    const float* Wv      = (const float*)d_in[7];
    const float* bv      = (const float*)d_in[8];
    const float* Wo      = (const float*)d_in[9];
    const float* bo      = (const float*)d_in[10];
    const float* readout = (const float*)d_in[11];
    float* out = (float*)d_out;
    (void)n_in;

    const int M  = in_sizes[0] / DMODEL;   // N*L = 32768
    const int Nb = out_size / DMODEL;      // 64
    const int L  = M / Nb;                 // 512

    float *gQ, *gK, *gV, *gO;
    cudaGetSymbolAddress((void**)&gQ, g_Q);
    cudaGetSymbolAddress((void**)&gK, g_K);
    cudaGetSymbolAddress((void**)&gV, g_V);
    cudaGetSymbolAddress((void**)&gO, g_O);

    dim3 gg(DMODEL / GBN, M / GBM);
    gemm_tc<<<gg, 256>>>(tokens, Wq, bq, nullptr, gQ, M, DMODEL, DMODEL);
    gemm_tc<<<gg, 256>>>(tokens, Wk, bk, nullptr, gK, M, DMODEL, DMODEL);
    gemm_tc<<<gg, 256>>>(tokens, Wv, bv, nullptr, gV, M, DMODEL, DMODEL);

    const int smem = (4096 + 4224 + 4096 + 4096 + 192) * 4;   // 66816 B
    cudaFuncSetAttribute(attn_kernel, cudaFuncAttributeMaxDynamicSharedMemorySize, smem);
    dim3 ag(L / 64, NHEAD, Nb);
    attn_kernel<<<ag, 256, smem>>>(gQ, gK, gV, ts, maskp, gO, L);

    // projected + masked output reuses g_Q
    gemm_tc<<<gg, 256>>>(gO, Wo, bo, maskp, gQ, M, DMODEL, DMODEL);

    dim3 pg(NHEAD, Nb);
    pool_kernel<<<pg, 256>>>(gQ, readout, maskp, out, L);
}

// round 4
// speedup vs baseline: 2.1638x; 1.3155x over previous
#include <cuda_runtime.h>
#include <cuda_bf16.h>
#include <math.h>
#include <stdint.h>

#define DMODEL 768
#define NHEAD  12
#define DH     64
#define TAU    300.0f
#define INV_TAU (1.0f / 300.0f)
#define NEGV   (-1e9f)
#define SCALE  0.125f   /* 1/sqrt(64) */

#define MAXM (64 * 512)

__device__ float g_Q[MAXM * DMODEL];
__device__ float g_K[MAXM * DMODEL];
__device__ float g_V[MAXM * DMODEL];
__device__ float g_O[MAXM * DMODEL];

// ===========================================================================
// mma.sync / ldmatrix helpers (HMMA path on sm_103a)
// ===========================================================================
__device__ __forceinline__ uint32_t smem_u32(const void* p) {
    uint32_t a;
    asm("{ .reg .u64 t; cvta.to.shared.u64 t, %1; cvt.u32.u64 %0, t; }"
        : "=r"(a) : "l"(p));
    return a;
}

__device__ __forceinline__ void ldsm4(uint32_t* r, uint32_t addr) {
    asm volatile("ldmatrix.sync.aligned.m8n8.x4.shared.b16 {%0,%1,%2,%3}, [%4];"
                 : "=r"(r[0]), "=r"(r[1]), "=r"(r[2]), "=r"(r[3]) : "r"(addr));
}

__device__ __forceinline__ void mma16816(float* c, const uint32_t* a,
                                         const uint32_t* b) {
    asm volatile(
        "mma.sync.aligned.m16n8k16.row.col.f32.bf16.bf16.f32 "
        "{%0,%1,%2,%3}, {%4,%5,%6,%7}, {%8,%9}, {%0,%1,%2,%3};"
        : "+f"(c[0]), "+f"(c[1]), "+f"(c[2]), "+f"(c[3])
        : "r"(a[0]), "r"(a[1]), "r"(a[2]), "r"(a[3]), "r"(b[0]), "r"(b[1]));
}

__device__ __forceinline__ void split4(float4 v, uint2& h, uint2& l) {
    __nv_bfloat16 h0 = __float2bfloat16_rn(v.x);
    __nv_bfloat16 h1 = __float2bfloat16_rn(v.y);
    __nv_bfloat16 h2 = __float2bfloat16_rn(v.z);
    __nv_bfloat16 h3 = __float2bfloat16_rn(v.w);
    __nv_bfloat16 l0 = __float2bfloat16_rn(v.x - __bfloat162float(h0));
    __nv_bfloat16 l1 = __float2bfloat16_rn(v.y - __bfloat162float(h1));
    __nv_bfloat16 l2 = __float2bfloat16_rn(v.z - __bfloat162float(h2));
    __nv_bfloat16 l3 = __float2bfloat16_rn(v.w - __bfloat162float(h3));
    h.x = (uint32_t)__bfloat16_as_ushort(h0) | ((uint32_t)__bfloat16_as_ushort(h1) << 16);
    h.y = (uint32_t)__bfloat16_as_ushort(h2) | ((uint32_t)__bfloat16_as_ushort(h3) << 16);
    l.x = (uint32_t)__bfloat16_as_ushort(l0) | ((uint32_t)__bfloat16_as_ushort(l1) << 16);
    l.y = (uint32_t)__bfloat16_as_ushort(l2) | ((uint32_t)__bfloat16_as_ushort(l3) << 16);
}

__device__ __forceinline__ uint32_t pack_bf16(float a, float b) {
    __nv_bfloat162 t = __floats2bfloat162_rn(a, b);
    return *(uint32_t*)&t;
}
__device__ __forceinline__ void split2(float a, float b, uint32_t& h, uint32_t& l) {
    __nv_bfloat16 ha = __float2bfloat16_rn(a);
    __nv_bfloat16 hb = __float2bfloat16_rn(b);
    float la = a - __bfloat162float(ha);
    float lb = b - __bfloat162float(hb);
    h = (uint32_t)__bfloat16_as_ushort(ha) | ((uint32_t)__bfloat16_as_ushort(hb) << 16);
    l = pack_bf16(la, lb);
}

// ===========================================================================
// HMMA GEMM (unchanged from R3, validated): C = A @ W^T + bias, opt * mask
// ===========================================================================
#define GBM 128
#define GBN 128
#define GBK 32
#define GPITCH 40

__global__ __launch_bounds__(256, 1) void gemm_tc(
    const float* __restrict__ A, const float* __restrict__ W,
    const float* __restrict__ bias, const float* __restrict__ maskp,
    float* __restrict__ C, int M, int N, int K)
{
    __shared__ __nv_bfloat16 Ah[GBM * GPITCH], Al[GBM * GPITCH];
    __shared__ __nv_bfloat16 Bh[GBN * GPITCH], Bl[GBN * GPITCH];
    __shared__ float bias_s[GBN];

    const int t = threadIdx.x;
    const int wid = t >> 5, lane = t & 31;
    const int n0 = blockIdx.x * GBN;
    const int m0 = blockIdx.y * GBM;

    if (t < GBN) bias_s[t] = bias[n0 + t];

    const int lr = t >> 3;
    const int lc = t & 7;
    const float* Abase = A + (size_t)(m0 + lr) * K + lc * 4;
    const float* Wbase = W + (size_t)(n0 + lr) * K + lc * 4;

    float4 pa[4], pb[4];
    const int NITER = K / GBK;

#pragma unroll
    for (int i = 0; i < 4; i++) {
        pa[i] = *(const float4*)(Abase + (size_t)(32 * i) * K);
        pb[i] = *(const float4*)(Wbase + (size_t)(32 * i) * K);
    }

    const int wm = wid >> 2;
    const int wn = wid & 3;
    const uint32_t ah_s = smem_u32(Ah), al_s = smem_u32(Al);
    const uint32_t bh_s = smem_u32(Bh), bl_s = smem_u32(Bl);
    const int a_row = lane & 15;
    const int a_chk = (lane >> 4) & 1;
    const int b_n   = (lane & 7) + ((lane >> 4) & 1) * 8;
    const int b_chk = (lane >> 3) & 1;

    float acc[4][4][4];
#pragma unroll
    for (int mi = 0; mi < 4; mi++)
#pragma unroll
        for (int ni = 0; ni < 4; ni++)
#pragma unroll
            for (int j = 0; j < 4; j++) acc[mi][ni][j] = 0.0f;

    for (int it = 0; it < NITER; it++) {
#pragma unroll
        for (int i = 0; i < 4; i++) {
            int idx = (lr + 32 * i) * GPITCH + lc * 4;
            uint2 h, l;
            split4(pa[i], h, l);
            *(uint2*)&Ah[idx] = h;
            *(uint2*)&Al[idx] = l;
            split4(pb[i], h, l);
            *(uint2*)&Bh[idx] = h;
            *(uint2*)&Bl[idx] = l;
        }
        __syncthreads();

        if (it + 1 < NITER) {
            const float* An = Abase + (size_t)(it + 1) * GBK;
            const float* Wn = Wbase + (size_t)(it + 1) * GBK;
#pragma unroll
            for (int i = 0; i < 4; i++) {
                pa[i] = *(const float4*)(An + (size_t)(32 * i) * K);
                pb[i] = *(const float4*)(Wn + (size_t)(32 * i) * K);
            }
        }

#pragma unroll
        for (int s = 0; s < 2; s++) {
            uint32_t bhf[8], blf[8];
#pragma unroll
            for (int nt = 0; nt < 2; nt++) {
                uint32_t boff = (uint32_t)(wn * 32 + nt * 16 + b_n) * 80
                              + s * 32 + b_chk * 16;
                ldsm4(bhf + nt * 4, bh_s + boff);
                ldsm4(blf + nt * 4, bl_s + boff);
            }
#pragma unroll
            for (int mi = 0; mi < 4; mi++) {
                uint32_t aoff = (uint32_t)(wm * 64 + mi * 16 + a_row) * 80
                              + s * 32 + a_chk * 16;
                uint32_t ahf[4], alf[4];
                ldsm4(ahf, ah_s + aoff);
                ldsm4(alf, al_s + aoff);
#pragma unroll
                for (int ni = 0; ni < 4; ni++) {
                    mma16816(acc[mi][ni], ahf, bhf + ni * 2);
                    mma16816(acc[mi][ni], ahf, blf + ni * 2);
                    mma16816(acc[mi][ni], alf, bhf + ni * 2);
                }
            }
        }
        __syncthreads();
    }

    const int r0 = lane >> 2;
    const int c0 = (lane & 3) * 2;
#pragma unroll
    for (int mi = 0; mi < 4; mi++) {
        int mA = m0 + wm * 64 + mi * 16 + r0;
        int mB = mA + 8;
        float mkA = maskp ? maskp[mA] : 1.0f;
        float mkB = maskp ? maskp[mB] : 1.0f;
#pragma unroll
        for (int ni = 0; ni < 4; ni++) {
            int n = wn * 32 + ni * 8 + c0;
            float b0 = bias_s[n], b1 = bias_s[n + 1];
            float2 vA, vB;
            vA.x = (acc[mi][ni][0] + b0) * mkA;
            vA.y = (acc[mi][ni][1] + b1) * mkA;
            vB.x = (acc[mi][ni][2] + b0) * mkB;
            vB.y = (acc[mi][ni][3] + b1) * mkB;
            *(float2*)&C[(size_t)mA * N + n0 + n] = vA;
            *(float2*)&C[(size_t)mB * N + n0 + n] = vB;
        }
    }
}

// ===========================================================================
// Tensor-core flash attention. Block = (128 q-rows, head, batch), 8 warps,
// each warp owns 16 q-rows. K-chunks of 64. 3-term bf16 split on QK^T and PV.
// Bias = -|tq-tk|/tau (exact to 1.6e-7 vs log(exp()+1e-12) for dt/tau <= 12).
// Smem pitch 72 bf16 (144B) -> conflict-free ldmatrix rows.
// ===========================================================================
#define APITCH 72
// byte offsets in dynamic smem
#define A_QH 0
#define A_QL 18432
#define A_KH 36864
#define A_KL 46080
#define A_VH 55296
#define A_VL 64512
#define A_TK 73728
#define A_MK 73984
#define A_SMEM_TOTAL 74240

__global__ __launch_bounds__(256, 1) void attn_tc(
    const float* __restrict__ Q, const float* __restrict__ K,
    const float* __restrict__ V, const float* __restrict__ ts,
    const float* __restrict__ maskp, float* __restrict__ O, int L)
{
    extern __shared__ char smem[];
    __nv_bfloat16* Qh = (__nv_bfloat16*)(smem + A_QH);
    __nv_bfloat16* Ql = (__nv_bfloat16*)(smem + A_QL);
    __nv_bfloat16* Kh = (__nv_bfloat16*)(smem + A_KH);
    __nv_bfloat16* Kl = (__nv_bfloat16*)(smem + A_KL);
    __nv_bfloat16* Vh = (__nv_bfloat16*)(smem + A_VH);   // [d][key]
    __nv_bfloat16* Vl = (__nv_bfloat16*)(smem + A_VL);
    float* tks = (float*)(smem + A_TK);
    float* mks = (float*)(smem + A_MK);

    const int t = threadIdx.x, w = t >> 5, lane = t & 31;
    const int q0 = blockIdx.x * 128, h = blockIdx.y, n = blockIdx.z;
    const size_t base = (size_t)n * L * DMODEL + (size_t)h * DH;

    // ---- Q load + scale + split ----
    for (int idx = t; idx < 128 * 16; idx += 256) {
        int row = idx >> 4, q4 = idx & 15;
        float4 v = *(const float4*)(Q + base + (size_t)(q0 + row) * DMODEL + q4 * 4);
        v.x *= SCALE; v.y *= SCALE; v.z *= SCALE; v.w *= SCALE;
        uint2 hh, ll;
        split4(v, hh, ll);
        *(uint2*)&Qh[row * APITCH + q4 * 4] = hh;
        *(uint2*)&Ql[row * APITCH + q4 * 4] = ll;
    }
    __syncthreads();

    // ---- preload Q fragments (warp's 16 rows, all 4 k-steps) ----
    const int a_row = lane & 15, a_chk = (lane >> 4) & 1;
    const uint32_t qh_s = smem_u32(Qh), ql_s = smem_u32(Ql);
    uint32_t qhf[4][4], qlf[4][4];
#pragma unroll
    for (int ks = 0; ks < 4; ks++) {
        uint32_t aoff = (uint32_t)(w * 16 + a_row) * 144 + ks * 32 + a_chk * 16;
        ldsm4(qhf[ks], qh_s + aoff);
        ldsm4(qlf[ks], ql_s + aoff);
    }

    const int r0 = lane >> 2, c2 = (lane & 3) * 2;
    const float tq0 = ts[n * L + q0 + w * 16 + r0];
    const float tq1 = ts[n * L + q0 + w * 16 + r0 + 8];

    float o[8][4];
#pragma unroll
    for (int i = 0; i < 8; i++)
#pragma unroll
        for (int j = 0; j < 4; j++) o[i][j] = 0.0f;
    float m0 = -1e30f, m1 = -1e30f, l0 = 0.0f, l1 = 0.0f;

    const uint32_t kh_s = smem_u32(Kh), kl_s = smem_u32(Kl);
    const uint32_t vh_s = smem_u32(Vh), vl_s = smem_u32(Vl);
    const int b_n = (lane & 7) + ((lane >> 4) & 1) * 8;
    const int b_chk = (lane >> 3) & 1;

    const int nchunk = L / 64;
    for (int c = 0; c < nchunk; c++) {
        const int k0 = c * 64;
        __syncthreads();
        // ---- K chunk load/split ----
        for (int idx = t; idx < 64 * 16; idx += 256) {
            int row = idx >> 4, q4 = idx & 15;
            float4 v = *(const float4*)(K + base + (size_t)(k0 + row) * DMODEL + q4 * 4);
            uint2 hh, ll;
            split4(v, hh, ll);
            *(uint2*)&Kh[row * APITCH + q4 * 4] = hh;
            *(uint2*)&Kl[row * APITCH + q4 * 4] = ll;
        }
        // ---- V chunk load, transpose to [d][key], split ----
        {
            const int d = t & 63, kg = t >> 6;   // 16 keys per thread
            uint32_t hbuf[8], lbuf[8];
#pragma unroll
            for (int i = 0; i < 8; i++) {
                float va = V[base + (size_t)(k0 + kg * 16 + 2 * i)     * DMODEL + d];
                float vb = V[base + (size_t)(k0 + kg * 16 + 2 * i + 1) * DMODEL + d];
                split2(va, vb, hbuf[i], lbuf[i]);
            }
#pragma unroll
            for (int i = 0; i < 4; i++) {
                uint2 hh = make_uint2(hbuf[2 * i], hbuf[2 * i + 1]);
                uint2 ll = make_uint2(lbuf[2 * i], lbuf[2 * i + 1]);
                *(uint2*)&Vh[d * APITCH + kg * 16 + i * 4] = hh;
                *(uint2*)&Vl[d * APITCH + kg * 16 + i * 4] = ll;
            }
        }
        if (t < 64) {
            tks[t] = ts[n * L + k0 + t];
            mks[t] = maskp[n * L + k0 + t];
        }
        __syncthreads();

        // ---- S = Q K^T (3-term split) ----
        float S[8][4];
#pragma unroll
        for (int i = 0; i < 8; i++)
#pragma unroll
            for (int j = 0; j < 4; j++) S[i][j] = 0.0f;
#pragma unroll
        for (int ks = 0; ks < 4; ks++) {
#pragma unroll
            for (int g = 0; g < 4; g++) {
                uint32_t boff = (uint32_t)(g * 16 + b_n) * 144 + ks * 32 + b_chk * 16;
                uint32_t bh[4], bl[4];
                ldsm4(bh, kh_s + boff);
                ldsm4(bl, kl_s + boff);
#pragma unroll
                for (int ni = 0; ni < 2; ni++) {
                    mma16816(S[g * 2 + ni], qhf[ks], bh + ni * 2);
                    mma16816(S[g * 2 + ni], qhf[ks], bl + ni * 2);
                    mma16816(S[g * 2 + ni], qlf[ks], bh + ni * 2);
                }
            }
        }

        // ---- bias + mask + online softmax ----
        float cm0 = -1e30f, cm1 = -1e30f;
#pragma unroll
        for (int nt = 0; nt < 8; nt++) {
#pragma unroll
            for (int j = 0; j < 2; j++) {
                int key = nt * 8 + c2 + j;
                float tk = tks[key];
                bool ok = mks[key] > 0.0f;
                float bA = -fabsf(tq0 - tk) * INV_TAU;
                float bB = -fabsf(tq1 - tk) * INV_TAU;
                S[nt][j]     = ok ? S[nt][j]     + bA : NEGV;
                S[nt][j + 2] = ok ? S[nt][j + 2] + bB : NEGV;
                cm0 = fmaxf(cm0, S[nt][j]);
                cm1 = fmaxf(cm1, S[nt][j + 2]);
            }
        }
#pragma unroll
        for (int off = 1; off <= 2; off <<= 1) {
            cm0 = fmaxf(cm0, __shfl_xor_sync(0xffffffffu, cm0, off));
            cm1 = fmaxf(cm1, __shfl_xor_sync(0xffffffffu, cm1, off));
        }
        float nm0 = fmaxf(m0, cm0), nm1 = fmaxf(m1, cm1);
        float cr0 = __expf(m0 - nm0), cr1 = __expf(m1 - nm1);
        m0 = nm0; m1 = nm1;

        float ps0 = 0.0f, ps1 = 0.0f;
#pragma unroll
        for (int nt = 0; nt < 8; nt++) {
            float p00 = __expf(S[nt][0] - nm0);
            float p01 = __expf(S[nt][1] - nm0);
            float p10 = __expf(S[nt][2] - nm1);
            float p11 = __expf(S[nt][3] - nm1);
            ps0 += p00 + p01; ps1 += p10 + p11;
            S[nt][0] = p00; S[nt][1] = p01; S[nt][2] = p10; S[nt][3] = p11;
        }
#pragma unroll
        for (int off = 1; off <= 2; off <<= 1) {
            ps0 += __shfl_xor_sync(0xffffffffu, ps0, off);
            ps1 += __shfl_xor_sync(0xffffffffu, ps1, off);
        }
        l0 = l0 * cr0 + ps0;
        l1 = l1 * cr1 + ps1;

#pragma unroll
        for (int i = 0; i < 8; i++) {
            o[i][0] *= cr0; o[i][1] *= cr0;
            o[i][2] *= cr1; o[i][3] *= cr1;
        }

        // ---- O += P V (3-term split; P frags from registers) ----
#pragma unroll
        for (int kt = 0; kt < 4; kt++) {
            uint32_t pah[4], pal[4];
            split2(S[2 * kt][0],     S[2 * kt][1],     pah[0], pal[0]);
            split2(S[2 * kt][2],     S[2 * kt][3],     pah[1], pal[1]);
            split2(S[2 * kt + 1][0], S[2 * kt + 1][1], pah[2], pal[2]);
            split2(S[2 * kt + 1][2], S[2 * kt + 1][3], pah[3], pal[3]);
#pragma unroll
            for (int g = 0; g < 4; g++) {
                uint32_t boff = (uint32_t)(g * 16 + b_n) * 144 + kt * 32 + b_chk * 16;
                uint32_t bh[4], bl[4];
                ldsm4(bh, vh_s + boff);
                ldsm4(bl, vl_s + boff);
#pragma unroll
                for (int ni = 0; ni < 2; ni++) {
                    mma16816(o[g * 2 + ni], pah, bh + ni * 2);
                    mma16816(o[g * 2 + ni], pal, bh + ni * 2);
                    mma16816(o[g * 2 + ni], pah, bl + ni * 2);
                }
            }
        }
    }

    // ---- normalize + store ----
    const float inv0 = 1.0f / l0, inv1 = 1.0f / l1;
    const int gr0 = q0 + w * 16 + r0, gr1 = gr0 + 8;
#pragma unroll
    for (int ntd = 0; ntd < 8; ntd++) {
        int d = ntd * 8 + c2;
        float2 vA = make_float2(o[ntd][0] * inv0, o[ntd][1] * inv0);
        float2 vB = make_float2(o[ntd][2] * inv1, o[ntd][3] * inv1);
        *(float2*)&O[base + (size_t)gr0 * DMODEL + d] = vA;
        *(float2*)&O[base + (size_t)gr1 * DMODEL + d] = vB;
    }
}

// ---------------------------------------------------------------------------
// Readout pooling: one block per (head, batch). X = masked projected output.
// ---------------------------------------------------------------------------
__global__ __launch_bounds__(256) void pool_kernel(
    const float* __restrict__ X, const float* __restrict__ readout,
    const float* __restrict__ maskp, float* __restrict__ out, int L)
{
    __shared__ float s[512];
    __shared__ float qsh[64];
    __shared__ float red[8];
    __shared__ float part[8][64];
    const int h = blockIdx.x, n = blockIdx.y;
    const int t = threadIdx.x, w = t >> 5, lane = t & 31;
    if (t < 64) qsh[t] = readout[h * DH + t] * SCALE;
    __syncthreads();
    const size_t base = (size_t)n * L * DMODEL + (size_t)h * DH;

    for (int k = w; k < L; k += 8) {
        float d = X[base + (size_t)k * DMODEL + lane] * qsh[lane]
                + X[base + (size_t)k * DMODEL + lane + 32] * qsh[lane + 32];
#pragma unroll
        for (int o = 16; o > 0; o >>= 1) d += __shfl_xor_sync(0xffffffffu, d, o);
        if (lane == 0) s[k] = (maskp[n * L + k] > 0.f) ? d : NEGV;
    }
    __syncthreads();

    float lm = -1e30f;
    for (int k = t; k < L; k += 256) lm = fmaxf(lm, s[k]);
#pragma unroll
    for (int o = 16; o > 0; o >>= 1) lm = fmaxf(lm, __shfl_xor_sync(0xffffffffu, lm, o));
    if (lane == 0) red[w] = lm;
    __syncthreads();
    float gm = red[0];
#pragma unroll
    for (int i = 1; i < 8; i++) gm = fmaxf(gm, red[i]);
    __syncthreads();
    float ls = 0.f;
    for (int k = t; k < L; k += 256) { float p = expf(s[k] - gm); s[k] = p; ls += p; }
#pragma unroll
    for (int o = 16; o > 0; o >>= 1) ls += __shfl_xor_sync(0xffffffffu, ls, o);
    if (lane == 0) red[w] = ls;
    __syncthreads();
    float gs = 0.f;
#pragma unroll
    for (int i = 0; i < 8; i++) gs += red[i];
    float inv = 1.0f / gs;

    const int kb = w * (L / 8), ke = kb + (L / 8);
    float a0 = 0.f, a1 = 0.f;
    for (int k = kb; k < ke; k++) {
        float p = s[k];
        a0 = fmaf(p, X[base + (size_t)k * DMODEL + lane], a0);
        a1 = fmaf(p, X[base + (size_t)k * DMODEL + lane + 32], a1);
    }
    part[w][lane]      = a0;
    part[w][lane + 32] = a1;
    __syncthreads();
    if (t < 64) {
        float sum = 0.f;
#pragma unroll
        for (int i = 0; i < 8; i++) sum += part[i][t];
        out[(size_t)n * DMODEL + h * DH + t] = sum * inv;
    }
}

// ---------------------------------------------------------------------------
extern "C" void kernel_launch(void* const* d_in, const int* in_sizes, int n_in,
                              void* d_out, int out_size)
{
    const float* tokens  = (const float*)d_in[0];
    const float* ts      = (const float*)d_in[1];
    const float* maskp   = (const float*)d_in[2];
    const float* Wq      = (const float*)d_in[3];
    const float* bq      = (const float*)d_in[4];
    const float* Wk      = (const float*)d_in[5];
    const float* bk      = (const float*)d_in[6];
    const float* Wv      = (const float*)d_in[7];
    const float* bv      = (const float*)d_in[8];
    const float* Wo      = (const float*)d_in[9];
    const float* bo      = (const float*)d_in[10];
    const float* readout = (const float*)d_in[11];
    float* out = (float*)d_out;
    (void)n_in;

    const int M  = in_sizes[0] / DMODEL;   // N*L = 32768
    const int Nb = out_size / DMODEL;      // 64
    const int L  = M / Nb;                 // 512

    float *gQ, *gK, *gV, *gO;
    cudaGetSymbolAddress((void**)&gQ, g_Q);
    cudaGetSymbolAddress((void**)&gK, g_K);
    cudaGetSymbolAddress((void**)&gV, g_V);
    cudaGetSymbolAddress((void**)&gO, g_O);

    dim3 gg(DMODEL / GBN, M / GBM);
    gemm_tc<<<gg, 256>>>(tokens, Wq, bq, nullptr, gQ, M, DMODEL, DMODEL);
    gemm_tc<<<gg, 256>>>(tokens, Wk, bk, nullptr, gK, M, DMODEL, DMODEL);
    gemm_tc<<<gg, 256>>>(tokens, Wv, bv, nullptr, gV, M, DMODEL, DMODEL);

    cudaFuncSetAttribute(attn_tc, cudaFuncAttributeMaxDynamicSharedMemorySize,
                         A_SMEM_TOTAL);
    dim3 ag(L / 128, NHEAD, Nb);
    attn_tc<<<ag, 256, A_SMEM_TOTAL>>>(gQ, gK, gV, ts, maskp, gO, L);

    gemm_tc<<<gg, 256>>>(gO, Wo, bo, maskp, gQ, M, DMODEL, DMODEL);

    dim3 pg(NHEAD, Nb);
    pool_kernel<<<pg, 256>>>(gQ, readout, maskp, out, L);
}